// round 2
// baseline (speedup 1.0000x reference)
#include <cuda_runtime.h>
#include <cstdint>
#include <cstddef>

#define DI __device__ __forceinline__

// ---------------- constants ----------------
constexpr int BM = 128, BN = 128, BK = 32, STAGES = 4, THREADS = 256;
constexpr int DIMK = 1024;          // D_IN == D_OUT
constexpr int BATCH = 16384;
constexpr int CHUNKS = 64;          // K_total 2048 / BK
constexpr size_t PLANE = (size_t)BATCH * DIMK;   // 16,777,216 elements per gate

constexpr uint32_t A_BYTES = 128 * 128;          // 128 rows x 32 tf32 x 4B
constexpr uint32_t B_STRIDE = 544;               // 128 floats + 32B pad (bank-conflict-free)
constexpr uint32_t B_BYTES = 32 * B_STRIDE;      // 17408
constexpr uint32_t STG = A_BYTES + B_BYTES;      // 33792 per stage
constexpr uint32_t SMEM_TOTAL = STAGES * STG;    // 135168

// z scratch: 4 gates of [16384 x 1024] fp32 pre-activations (static: allowed)
__device__ float g_z[4 * PLANE];

// ---------------- PTX helpers (baseline sm_80+ features only) ----------------
DI uint32_t smem_u32(const void* p) {
    uint32_t a;
    asm("{ .reg .u64 t; cvta.to.shared.u64 t, %1; cvt.u32.u64 %0, t; }" : "=r"(a) : "l"(p));
    return a;
}
DI uint32_t sw128(uint32_t o) { return o ^ ((o >> 3) & 0x70); }
DI void cpasync16(uint32_t dst, const void* src) {
    asm volatile("cp.async.cg.shared.global [%0], [%1], 16;" :: "r"(dst), "l"(src) : "memory");
}
DI void cpcommit() { asm volatile("cp.async.commit_group;" ::: "memory"); }
template<int N> DI void cpwait() { asm volatile("cp.async.wait_group %0;" :: "n"(N) : "memory"); }
DI void ldsm4(uint32_t* r, uint32_t a) {
    asm volatile("ldmatrix.sync.aligned.m8n8.x4.shared.b16 {%0,%1,%2,%3}, [%4];"
                 : "=r"(r[0]), "=r"(r[1]), "=r"(r[2]), "=r"(r[3]) : "r"(a));
}
DI uint32_t lds32(uint32_t a) {
    uint32_t v;
    asm volatile("ld.shared.b32 %0, [%1];" : "=r"(v) : "r"(a));
    return v;
}
DI void mma8(float* d, const uint32_t* a, uint32_t b0, uint32_t b1) {
    asm volatile(
        "mma.sync.aligned.m16n8k8.row.col.f32.tf32.tf32.f32 "
        "{%0,%1,%2,%3},{%4,%5,%6,%7},{%8,%9},{%0,%1,%2,%3};"
        : "+f"(d[0]), "+f"(d[1]), "+f"(d[2]), "+f"(d[3])
        : "r"(a[0]), "r"(a[1]), "r"(a[2]), "r"(a[3]), "r"(b0), "r"(b1));
}

// ---------------- GEMM: z[gate] = [X|H] @ [Wx;Wh] (tf32 HMMA) ----------------
__global__ void __launch_bounds__(THREADS)
lstm_gemm(const float* __restrict__ X, const float* __restrict__ H,
          const float* __restrict__ Wfx, const float* __restrict__ Wfh,
          const float* __restrict__ Wix, const float* __restrict__ Wih,
          const float* __restrict__ Wox, const float* __restrict__ Woh,
          const float* __restrict__ Wcx, const float* __restrict__ Wch)
{
    extern __shared__ __align__(1024) char smem[];
    const uint32_t sbase = smem_u32(smem);
    const int tid = threadIdx.x, wid = tid >> 5, lane = tid & 31;

    // consecutive CTAs share the same m-tile (A reuse across 32 CTAs in a wave)
    const int nt = blockIdx.x & 31;
    const int m0 = (blockIdx.x >> 5) * BM;
    const int gate = nt >> 3;
    const int n0 = (nt & 7) * BN;

    const float* Wx = (gate == 0) ? Wfx : (gate == 1) ? Wix : (gate == 2) ? Wox : Wcx;
    const float* Wh = (gate == 0) ? Wfh : (gate == 1) ? Wih : (gate == 2) ? Woh : Wch;

    const int warp_m = (wid & 1) * 64;
    const int warp_n = (wid >> 1) * 32;

    float acc[4][4][4];
    #pragma unroll
    for (int mi = 0; mi < 4; ++mi)
        #pragma unroll
        for (int j = 0; j < 4; ++j)
            #pragma unroll
            for (int e = 0; e < 4; ++e) acc[mi][j][e] = 0.f;

    auto stage = [&](int cs) {
        const uint32_t sb = sbase + (uint32_t)(cs & 3) * STG;
        const float* Asrc = (cs < 32) ? X : H;
        const float* Wsrc = (cs < 32) ? Wx : Wh;
        const int k0 = (cs & 31) * BK;
        #pragma unroll
        for (int i = 0; i < 4; ++i) {                 // A: 128 x 32, swizzled 128B rows
            const int idx = i * THREADS + tid;
            const int r = idx >> 3, c = idx & 7;
            cpasync16(sb + sw128((uint32_t)(r * 128 + c * 16)),
                      Asrc + (size_t)(m0 + r) * DIMK + k0 + c * 4);
        }
        #pragma unroll
        for (int i = 0; i < 4; ++i) {                 // B: 32 k-rows x 128 n, padded stride
            const int idx = i * THREADS + tid;
            const int kr = idx >> 5, nc = idx & 31;
            cpasync16(sb + A_BYTES + (uint32_t)(kr * B_STRIDE + nc * 16),
                      Wsrc + (size_t)(k0 + kr) * DIMK + n0 + nc * 4);
        }
    };

    // prologue: fill 3 stages
    #pragma unroll
    for (int s = 0; s < 3; ++s) { stage(s); cpcommit(); }

    #pragma unroll 1
    for (int cc = 0; cc < CHUNKS; ++cc) {
        cpwait<2>();
        __syncthreads();
        if (cc + 3 < CHUNKS) stage(cc + 3);
        cpcommit();

        const uint32_t Abuf = sbase + (uint32_t)(cc & 3) * STG;
        const uint32_t Bbuf = Abuf + A_BYTES;

        #pragma unroll
        for (int ks = 0; ks < 4; ++ks) {
            uint32_t a[4][4];
            #pragma unroll
            for (int mi = 0; mi < 4; ++mi) {
                const uint32_t addr = Abuf +
                    sw128((uint32_t)((warp_m + 16 * mi + (lane & 15)) * 128 + ks * 32 + (lane & 16)));
                ldsm4(a[mi], addr);
            }
            uint32_t b0[4], b1[4];
            #pragma unroll
            for (int j = 0; j < 4; ++j) {
                const uint32_t addr = Bbuf + (uint32_t)((8 * ks + (lane & 3)) * B_STRIDE
                                    + (warp_n + 8 * j + (lane >> 2)) * 4);
                b0[j] = lds32(addr);
                b1[j] = lds32(addr + 4 * B_STRIDE);
            }
            #pragma unroll
            for (int mi = 0; mi < 4; ++mi)
                #pragma unroll
                for (int j = 0; j < 4; ++j)
                    mma8(acc[mi][j], a[mi], b0[j], b1[j]);
        }
    }

    // store pre-activations to scratch
    float* zout = g_z + (size_t)gate * PLANE;
    #pragma unroll
    for (int mi = 0; mi < 4; ++mi) {
        #pragma unroll
        for (int j = 0; j < 4; ++j) {
            const int r = m0 + warp_m + 16 * mi + (lane >> 2);
            const int c = n0 + warp_n + 8 * j + (lane & 3) * 2;
            *reinterpret_cast<float2*>(zout + (size_t)r * DIMK + c) =
                make_float2(acc[mi][j][0], acc[mi][j][1]);
            *reinterpret_cast<float2*>(zout + (size_t)(r + 8) * DIMK + c) =
                make_float2(acc[mi][j][2], acc[mi][j][3]);
        }
    }
}

// ---------------- epilogue: gates + combine, fully coalesced ----------------
__global__ void __launch_bounds__(256)
lstm_epilogue(const int* __restrict__ caro,
              const float* __restrict__ bf, const float* __restrict__ bi,
              const float* __restrict__ bo, const float* __restrict__ bc,
              float* __restrict__ out)
{
    const float cf = (float)__ldg(caro);
    const size_t v = (size_t)blockIdx.x * blockDim.x + threadIdx.x;  // one float4 each
    const int col4 = (int)(v & (DIMK / 4 - 1));

    const float4 zf = reinterpret_cast<const float4*>(g_z)[v];
    const float4 zi = reinterpret_cast<const float4*>(g_z + PLANE)[v];
    const float4 zo = reinterpret_cast<const float4*>(g_z + 2 * PLANE)[v];
    const float4 zc = reinterpret_cast<const float4*>(g_z + 3 * PLANE)[v];
    const float4 vbf = reinterpret_cast<const float4*>(bf)[col4];
    const float4 vbi = reinterpret_cast<const float4*>(bi)[col4];
    const float4 vbo = reinterpret_cast<const float4*>(bo)[col4];
    const float4 vbc = reinterpret_cast<const float4*>(bc)[col4];

    float4 h4, c4;
    const float* pzf = &zf.x; const float* pzi = &zi.x;
    const float* pzo = &zo.x; const float* pzc = &zc.x;
    const float* pbf = &vbf.x; const float* pbi = &vbi.x;
    const float* pbo = &vbo.x; const float* pbc = &vbc.x;
    float* ph = &h4.x; float* pc = &c4.x;
    #pragma unroll
    for (int e = 0; e < 4; ++e) {
        const float f  = 1.f / (1.f + expf(-(pzf[e] + pbf[e])));
        const float ii = 1.f / (1.f + expf(-(pzi[e] + pbi[e])));
        const float oo = 1.f / (1.f + expf(-(pzo[e] + pbo[e])));
        const float gg = tanhf(pzc[e] + pbc[e]);
        const float cv = f * cf + ii * gg;
        pc[e] = cv;
        ph[e] = oo * cv;
    }
    reinterpret_cast<float4*>(out)[v] = h4;
    reinterpret_cast<float4*>(out + PLANE)[v] = c4;
}

// ---------------- launch ----------------
extern "C" void kernel_launch(void* const* d_in, const int* in_sizes, int n_in,
                              void* d_out, int out_size) {
    (void)in_sizes; (void)n_in; (void)out_size;
    const float* X    = (const float*)d_in[0];
    const float* H    = (const float*)d_in[1];
    const int*   caro = (const int*)d_in[2];
    const float* Wfx = (const float*)d_in[3];
    const float* Wfh = (const float*)d_in[4];
    const float* bf  = (const float*)d_in[5];
    const float* Wix = (const float*)d_in[6];
    const float* Wih = (const float*)d_in[7];
    const float* bi  = (const float*)d_in[8];
    const float* Wox = (const float*)d_in[9];
    const float* Woh = (const float*)d_in[10];
    const float* bo  = (const float*)d_in[11];
    const float* Wcx = (const float*)d_in[12];
    const float* Wch = (const float*)d_in[13];
    const float* bc  = (const float*)d_in[14];
    float* out = (float*)d_out;

    cudaFuncSetAttribute(lstm_gemm, cudaFuncAttributeMaxDynamicSharedMemorySize, SMEM_TOTAL);

    const int grid_gemm = (BATCH / BM) * 32;   // 128 m-tiles * (8 n-tiles * 4 gates) = 4096
    lstm_gemm<<<grid_gemm, THREADS, SMEM_TOTAL>>>(X, H, Wfx, Wfh, Wix, Wih, Wox, Woh, Wcx, Wch);

    const int grid_epi = (int)(PLANE / 4 / 256);  // 16384 blocks, one float4/thread
    lstm_epilogue<<<grid_epi, 256>>>(caro, bf, bi, bo, bc, out);
}

// round 3
// speedup vs baseline: 1.1869x; 1.1869x over previous
#include <cuda_runtime.h>
#include <cstdint>
#include <cstddef>

#define DI __device__ __forceinline__

// ---------------- constants ----------------
constexpr int BM = 128, BN = 128, BK = 32, THREADS = 256;
constexpr int DIMK = 1024;          // D_IN == D_OUT
constexpr int BATCH = 16384;
constexpr int CHUNKS = 64;          // K_total 2048 / BK
constexpr size_t PLANE = (size_t)BATCH * DIMK;   // 16,777,216 elements per gate

constexpr uint32_t A_BYTES = 128 * 128;          // 128 rows x 32 tf32 x 4B
constexpr uint32_t B_STRIDE = 544;               // 128 floats + 32B pad (bank-conflict-free)
constexpr uint32_t B_BYTES = 32 * B_STRIDE;      // 17408
constexpr uint32_t STG = A_BYTES + B_BYTES;      // 33792 per stage
constexpr uint32_t SMEM_TOTAL = 3 * STG;         // 101376 -> 2 CTAs/SM (203KB < 228KB)

// z scratch: 4 gates of [16384 x 1024] fp32 pre-activations (static: allowed)
__device__ float g_z[4 * PLANE];

// ---------------- PTX helpers (baseline sm_80+ features only) ----------------
DI uint32_t smem_u32(const void* p) {
    uint32_t a;
    asm("{ .reg .u64 t; cvta.to.shared.u64 t, %1; cvt.u32.u64 %0, t; }" : "=r"(a) : "l"(p));
    return a;
}
DI uint32_t sw128(uint32_t o) { return o ^ ((o >> 3) & 0x70); }
DI void cpasync16(uint32_t dst, const void* src) {
    asm volatile("cp.async.cg.shared.global [%0], [%1], 16;" :: "r"(dst), "l"(src) : "memory");
}
DI void cpcommit() { asm volatile("cp.async.commit_group;" ::: "memory"); }
template<int N> DI void cpwait() { asm volatile("cp.async.wait_group %0;" :: "n"(N) : "memory"); }
DI void ldsm4(uint32_t* r, uint32_t a) {
    asm volatile("ldmatrix.sync.aligned.m8n8.x4.shared.b16 {%0,%1,%2,%3}, [%4];"
                 : "=r"(r[0]), "=r"(r[1]), "=r"(r[2]), "=r"(r[3]) : "r"(a));
}
DI uint32_t lds32(uint32_t a) {
    uint32_t v;
    asm volatile("ld.shared.b32 %0, [%1];" : "=r"(v) : "r"(a));
    return v;
}
DI void mma8(float* d, const uint32_t* a, uint32_t b0, uint32_t b1) {
    asm volatile(
        "mma.sync.aligned.m16n8k8.row.col.f32.tf32.tf32.f32 "
        "{%0,%1,%2,%3},{%4,%5,%6,%7},{%8,%9},{%0,%1,%2,%3};"
        : "+f"(d[0]), "+f"(d[1]), "+f"(d[2]), "+f"(d[3])
        : "r"(a[0]), "r"(a[1]), "r"(a[2]), "r"(a[3]), "r"(b0), "r"(b1));
}

// ---------------- GEMM: z[gate] = [X|H] @ [Wx;Wh] (tf32 HMMA) ----------------
__global__ void __launch_bounds__(THREADS, 2)
lstm_gemm(const float* __restrict__ X, const float* __restrict__ H,
          const float* __restrict__ Wfx, const float* __restrict__ Wfh,
          const float* __restrict__ Wix, const float* __restrict__ Wih,
          const float* __restrict__ Wox, const float* __restrict__ Woh,
          const float* __restrict__ Wcx, const float* __restrict__ Wch)
{
    extern __shared__ __align__(1024) char smem[];
    const uint32_t sbase = smem_u32(smem);
    const int tid = threadIdx.x, wid = tid >> 5, lane = tid & 31;

    // consecutive CTAs share the same m-tile (A reuse across 32 CTAs in a wave)
    const int nt = blockIdx.x & 31;
    const int m0 = (blockIdx.x >> 5) * BM;
    const int gate = nt >> 3;
    const int n0 = (nt & 7) * BN;

    const float* Wx = (gate == 0) ? Wfx : (gate == 1) ? Wix : (gate == 2) ? Wox : Wcx;
    const float* Wh = (gate == 0) ? Wfh : (gate == 1) ? Wih : (gate == 2) ? Woh : Wch;

    const int warp_m = (wid & 1) * 64;
    const int warp_n = (wid >> 1) * 32;

    float acc[4][4][4];
    #pragma unroll
    for (int mi = 0; mi < 4; ++mi)
        #pragma unroll
        for (int j = 0; j < 4; ++j)
            #pragma unroll
            for (int e = 0; e < 4; ++e) acc[mi][j][e] = 0.f;

    auto stage = [&](int cs, uint32_t sb) {
        const float* Asrc = (cs < 32) ? X : H;
        const float* Wsrc = (cs < 32) ? Wx : Wh;
        const int k0 = (cs & 31) * BK;
        #pragma unroll
        for (int i = 0; i < 4; ++i) {                 // A: 128 x 32, swizzled 128B rows
            const int idx = i * THREADS + tid;
            const int r = idx >> 3, c = idx & 7;
            cpasync16(sb + sw128((uint32_t)(r * 128 + c * 16)),
                      Asrc + (size_t)(m0 + r) * DIMK + k0 + c * 4);
        }
        #pragma unroll
        for (int i = 0; i < 4; ++i) {                 // B: 32 k-rows x 128 n, padded stride
            const int idx = i * THREADS + tid;
            const int kr = idx >> 5, nc = idx & 31;
            cpasync16(sb + A_BYTES + (uint32_t)(kr * B_STRIDE + nc * 16),
                      Wsrc + (size_t)(k0 + kr) * DIMK + n0 + nc * 4);
        }
    };

    // prologue: fill 2 of 3 stages
    stage(0, sbase);            cpcommit();
    stage(1, sbase + STG);      cpcommit();

    uint32_t cur = 0, nxt = 2 * STG;  // rotating smem stage offsets
    #pragma unroll 1
    for (int cc = 0; cc < CHUNKS; ++cc) {
        cpwait<1>();
        __syncthreads();
        if (cc + 2 < CHUNKS) stage(cc + 2, sbase + nxt);
        cpcommit();

        const uint32_t Abuf = sbase + cur;
        const uint32_t Bbuf = Abuf + A_BYTES;
        nxt = cur;
        cur = (cur == 2 * STG) ? 0 : cur + STG;

        #pragma unroll
        for (int ks = 0; ks < 4; ++ks) {
            uint32_t a[4][4];
            #pragma unroll
            for (int mi = 0; mi < 4; ++mi) {
                const uint32_t addr = Abuf +
                    sw128((uint32_t)((warp_m + 16 * mi + (lane & 15)) * 128 + ks * 32 + (lane & 16)));
                ldsm4(a[mi], addr);
            }
            uint32_t b0[4], b1[4];
            #pragma unroll
            for (int j = 0; j < 4; ++j) {
                const uint32_t addr = Bbuf + (uint32_t)((8 * ks + (lane & 3)) * B_STRIDE
                                    + (warp_n + 8 * j + (lane >> 2)) * 4);
                b0[j] = lds32(addr);
                b1[j] = lds32(addr + 4 * B_STRIDE);
            }
            #pragma unroll
            for (int mi = 0; mi < 4; ++mi)
                #pragma unroll
                for (int j = 0; j < 4; ++j)
                    mma8(acc[mi][j], a[mi], b0[j], b1[j]);
        }
    }

    // store pre-activations to scratch
    float* zout = g_z + (size_t)gate * PLANE;
    #pragma unroll
    for (int mi = 0; mi < 4; ++mi) {
        #pragma unroll
        for (int j = 0; j < 4; ++j) {
            const int r = m0 + warp_m + 16 * mi + (lane >> 2);
            const int c = n0 + warp_n + 8 * j + (lane & 3) * 2;
            *reinterpret_cast<float2*>(zout + (size_t)r * DIMK + c) =
                make_float2(acc[mi][j][0], acc[mi][j][1]);
            *reinterpret_cast<float2*>(zout + (size_t)(r + 8) * DIMK + c) =
                make_float2(acc[mi][j][2], acc[mi][j][3]);
        }
    }
}

// ---------------- epilogue: gates + combine, fully coalesced ----------------
__global__ void __launch_bounds__(256)
lstm_epilogue(const int* __restrict__ caro,
              const float* __restrict__ bf, const float* __restrict__ bi,
              const float* __restrict__ bo, const float* __restrict__ bc,
              float* __restrict__ out)
{
    const float cf = (float)__ldg(caro);
    const size_t v = (size_t)blockIdx.x * blockDim.x + threadIdx.x;  // one float4 each
    const int col4 = (int)(v & (DIMK / 4 - 1));

    const float4 zf = reinterpret_cast<const float4*>(g_z)[v];
    const float4 zi = reinterpret_cast<const float4*>(g_z + PLANE)[v];
    const float4 zo = reinterpret_cast<const float4*>(g_z + 2 * PLANE)[v];
    const float4 zc = reinterpret_cast<const float4*>(g_z + 3 * PLANE)[v];
    const float4 vbf = reinterpret_cast<const float4*>(bf)[col4];
    const float4 vbi = reinterpret_cast<const float4*>(bi)[col4];
    const float4 vbo = reinterpret_cast<const float4*>(bo)[col4];
    const float4 vbc = reinterpret_cast<const float4*>(bc)[col4];

    float4 h4, c4;
    const float* pzf = &zf.x; const float* pzi = &zi.x;
    const float* pzo = &zo.x; const float* pzc = &zc.x;
    const float* pbf = &vbf.x; const float* pbi = &vbi.x;
    const float* pbo = &vbo.x; const float* pbc = &vbc.x;
    float* ph = &h4.x; float* pc = &c4.x;
    #pragma unroll
    for (int e = 0; e < 4; ++e) {
        const float f  = 1.f / (1.f + expf(-(pzf[e] + pbf[e])));
        const float ii = 1.f / (1.f + expf(-(pzi[e] + pbi[e])));
        const float oo = 1.f / (1.f + expf(-(pzo[e] + pbo[e])));
        const float gg = tanhf(pzc[e] + pbc[e]);
        const float cv = f * cf + ii * gg;
        pc[e] = cv;
        ph[e] = oo * cv;
    }
    reinterpret_cast<float4*>(out)[v] = h4;
    reinterpret_cast<float4*>(out + PLANE)[v] = c4;
}

// ---------------- launch ----------------
extern "C" void kernel_launch(void* const* d_in, const int* in_sizes, int n_in,
                              void* d_out, int out_size) {
    (void)in_sizes; (void)n_in; (void)out_size;
    const float* X    = (const float*)d_in[0];
    const float* H    = (const float*)d_in[1];
    const int*   caro = (const int*)d_in[2];
    const float* Wfx = (const float*)d_in[3];
    const float* Wfh = (const float*)d_in[4];
    const float* bf  = (const float*)d_in[5];
    const float* Wix = (const float*)d_in[6];
    const float* Wih = (const float*)d_in[7];
    const float* bi  = (const float*)d_in[8];
    const float* Wox = (const float*)d_in[9];
    const float* Woh = (const float*)d_in[10];
    const float* bo  = (const float*)d_in[11];
    const float* Wcx = (const float*)d_in[12];
    const float* Wch = (const float*)d_in[13];
    const float* bc  = (const float*)d_in[14];
    float* out = (float*)d_out;

    cudaFuncSetAttribute(lstm_gemm, cudaFuncAttributeMaxDynamicSharedMemorySize, SMEM_TOTAL);

    const int grid_gemm = (BATCH / BM) * 32;   // 128 m-tiles * (8 n-tiles * 4 gates) = 4096
    lstm_gemm<<<grid_gemm, THREADS, SMEM_TOTAL>>>(X, H, Wfx, Wfh, Wix, Wih, Wox, Woh, Wcx, Wch);

    const int grid_epi = (int)(PLANE / 4 / 256);  // 16384 blocks, one float4/thread
    lstm_epilogue<<<grid_epi, 256>>>(caro, bf, bi, bo, bc, out);
}